// round 1
// baseline (speedup 1.0000x reference)
#include <cuda_runtime.h>
#include <math.h>

// Problem constants
#define Bq   4
#define Nq   1024
#define Cq   512
#define Hq   8
#define HDq  64
#define BHq  32          // B*H
#define Mq   4096        // B*N
#define SCALEq 0.125f    // HD^-0.5
#define LN_EPSq 1e-5f

// Scratch (device globals — allocation-free)
__device__ float g_q [BHq * Nq * HDq];   // [bh][n][d]
__device__ float g_k [BHq * Nq * HDq];
__device__ float g_v [BHq * Nq * HDq];
__device__ float g_ao[Mq * Cq];          // attention output, [b*n][h*64+d]
__device__ float g_yp[Mq * Cq];          // pre-layernorm y

// ---------------------------------------------------------------------------
// Kernel 1: QKV GEMM.  x[4096,512] @ Wqkv[512,1536] + bqkv -> scatter q/k/v
// 128x128x8 tiles, 256 threads, 8x8 per thread.
// ---------------------------------------------------------------------------
__global__ __launch_bounds__(256) void k_qkv(const float* __restrict__ A,
                                             const float* __restrict__ Bm,
                                             const float* __restrict__ bias) {
    const int K = 512, Nn = 1536;
    __shared__ float As[8][128];
    __shared__ float Bs[8][128];
    int tid = threadIdx.x;
    int bx = blockIdx.x, by = blockIdx.y;
    int aRow = tid >> 1, aCol = (tid & 1) << 2;
    int bRow = tid >> 5, bCol = (tid & 31) << 2;
    int ty = tid >> 4, tx = tid & 15;

    float acc[8][8];
#pragma unroll
    for (int i = 0; i < 8; i++)
#pragma unroll
        for (int j = 0; j < 8; j++) acc[i][j] = 0.f;

    const float* Ap = A + (size_t)(by * 128 + aRow) * K + aCol;
    const float* Bp = Bm + (size_t)bRow * Nn + bx * 128 + bCol;

    for (int k0 = 0; k0 < K; k0 += 8) {
        float4 av = *(const float4*)(Ap + k0);
        As[aCol + 0][aRow] = av.x;
        As[aCol + 1][aRow] = av.y;
        As[aCol + 2][aRow] = av.z;
        As[aCol + 3][aRow] = av.w;
        *(float4*)&Bs[bRow][bCol] = *(const float4*)(Bp + (size_t)k0 * Nn);
        __syncthreads();
#pragma unroll
        for (int k = 0; k < 8; k++) {
            float a[8], b[8];
            *(float4*)&a[0] = *(const float4*)&As[k][ty * 8];
            *(float4*)&a[4] = *(const float4*)&As[k][ty * 8 + 4];
            *(float4*)&b[0] = *(const float4*)&Bs[k][tx * 8];
            *(float4*)&b[4] = *(const float4*)&Bs[k][tx * 8 + 4];
#pragma unroll
            for (int i = 0; i < 8; i++)
#pragma unroll
                for (int j = 0; j < 8; j++) acc[i][j] = fmaf(a[i], b[j], acc[i][j]);
        }
        __syncthreads();
    }

    // epilogue: scatter into q/k/v [bh][n][d]
#pragma unroll
    for (int i = 0; i < 8; i++) {
        int r = by * 128 + ty * 8 + i;
        int bb = r >> 10, n = r & 1023;
#pragma unroll
        for (int j = 0; j < 8; j++) {
            int c = bx * 128 + tx * 8 + j;
            float v = acc[i][j] + bias[c];
            int sel = c >> 9;
            int rem = c & 511;
            int h = rem >> 6, d = rem & 63;
            float* dst = (sel == 0) ? g_q : ((sel == 1) ? g_k : g_v);
            dst[((bb * 8 + h) * 1024 + n) * 64 + d] = v;
        }
    }
}

// ---------------------------------------------------------------------------
// Kernel 2: scores.  S = poly(ow; q·k^T * SCALE), written PRE-softmax to attn.
// One block per 64x64 output tile per (b,h). 256 threads, 4x4 per thread.
// ---------------------------------------------------------------------------
__global__ __launch_bounds__(256) void k_scores(const float* __restrict__ ow_in,
                                                float* __restrict__ attn) {
    __shared__ float Qt[64 * 68];  // [d][row], stride 68 (16B aligned, no conflicts)
    __shared__ float Kt[64 * 68];
    int bh = blockIdx.z;
    int mb = blockIdx.y * 64;
    int nb = blockIdx.x * 64;
    int tid = threadIdx.x;
    int lrow = tid >> 2;
    int ld0 = (tid & 3) << 4;

    const float* qp = g_q + (size_t)(bh * 1024 + mb + lrow) * 64 + ld0;
    const float* kp = g_k + (size_t)(bh * 1024 + nb + lrow) * 64 + ld0;
#pragma unroll
    for (int i = 0; i < 16; i += 4) {
        float4 qv = *(const float4*)(qp + i);
        Qt[(ld0 + i + 0) * 68 + lrow] = qv.x;
        Qt[(ld0 + i + 1) * 68 + lrow] = qv.y;
        Qt[(ld0 + i + 2) * 68 + lrow] = qv.z;
        Qt[(ld0 + i + 3) * 68 + lrow] = qv.w;
        float4 kv = *(const float4*)(kp + i);
        Kt[(ld0 + i + 0) * 68 + lrow] = kv.x;
        Kt[(ld0 + i + 1) * 68 + lrow] = kv.y;
        Kt[(ld0 + i + 2) * 68 + lrow] = kv.z;
        Kt[(ld0 + i + 3) * 68 + lrow] = kv.w;
    }
    __syncthreads();

    int ty = tid >> 4, tx = tid & 15;
    float acc[4][4];
#pragma unroll
    for (int i = 0; i < 4; i++)
#pragma unroll
        for (int j = 0; j < 4; j++) acc[i][j] = 0.f;

#pragma unroll
    for (int d = 0; d < 64; d++) {
        float4 a = *(const float4*)(Qt + d * 68 + ty * 4);
        float4 b = *(const float4*)(Kt + d * 68 + tx * 4);
        float av[4] = {a.x, a.y, a.z, a.w};
        float bv[4] = {b.x, b.y, b.z, b.w};
#pragma unroll
        for (int i = 0; i < 4; i++)
#pragma unroll
            for (int j = 0; j < 4; j++) acc[i][j] = fmaf(av[i], bv[j], acc[i][j]);
    }

    // softmax(order_weights) — 3 elements, trivial per-thread
    float w0 = ow_in[0], w1 = ow_in[1], w2 = ow_in[2];
    float mw = fmaxf(w0, fmaxf(w1, w2));
    float e0 = __expf(w0 - mw), e1 = __expf(w1 - mw), e2 = __expf(w2 - mw);
    float inv = 1.f / (e0 + e1 + e2);
    w0 = e0 * inv; w1 = e1 * inv; w2 = e2 * inv;

#pragma unroll
    for (int i = 0; i < 4; i++) {
        int row = bh * 1024 + mb + ty * 4 + i;
        float4 o;
        float s;
        s = acc[i][0] * SCALEq; o.x = s * (w0 + s * (w1 + s * w2));
        s = acc[i][1] * SCALEq; o.y = s * (w0 + s * (w1 + s * w2));
        s = acc[i][2] * SCALEq; o.z = s * (w0 + s * (w1 + s * w2));
        s = acc[i][3] * SCALEq; o.w = s * (w0 + s * (w1 + s * w2));
        *(float4*)(attn + (size_t)row * 1024 + nb + tx * 4) = o;
    }
}

// ---------------------------------------------------------------------------
// Kernel 3: row softmax in place on attn [32768 rows x 1024].
// ---------------------------------------------------------------------------
__global__ __launch_bounds__(256) void k_softmax(float* __restrict__ attn) {
    __shared__ float red[8];
    int row = blockIdx.x;
    int tid = threadIdx.x;
    float* p = attn + (size_t)row * 1024;
    float4 v = *(const float4*)(p + tid * 4);

    float m = fmaxf(fmaxf(v.x, v.y), fmaxf(v.z, v.w));
#pragma unroll
    for (int o = 16; o; o >>= 1) m = fmaxf(m, __shfl_xor_sync(0xffffffffu, m, o));
    int wid = tid >> 5, lane = tid & 31;
    if (lane == 0) red[wid] = m;
    __syncthreads();
    if (tid == 0) {
        float mm = red[0];
#pragma unroll
        for (int i = 1; i < 8; i++) mm = fmaxf(mm, red[i]);
        red[0] = mm;
    }
    __syncthreads();
    m = red[0];
    __syncthreads();

    float4 e;
    e.x = __expf(v.x - m); e.y = __expf(v.y - m);
    e.z = __expf(v.z - m); e.w = __expf(v.w - m);
    float s = e.x + e.y + e.z + e.w;
#pragma unroll
    for (int o = 16; o; o >>= 1) s += __shfl_xor_sync(0xffffffffu, s, o);
    if (lane == 0) red[wid] = s;
    __syncthreads();
    if (tid == 0) {
        float ss = 0.f;
#pragma unroll
        for (int i = 0; i < 8; i++) ss += red[i];
        red[0] = ss;
    }
    __syncthreads();
    float invs = 1.f / red[0];

    e.x *= invs; e.y *= invs; e.z *= invs; e.w *= invs;
    *(float4*)(p + tid * 4) = e;
}

// ---------------------------------------------------------------------------
// Kernel 4: out = attn @ V.  Per (b,h): [1024,1024]@[1024,64].
// Block = 64-row tile x full 64 cols; 256 threads, 4x4 per thread.
// ---------------------------------------------------------------------------
__global__ __launch_bounds__(256) void k_av(const float* __restrict__ attn) {
    __shared__ float At[64 * 68];  // transposed attn tile [k][row]
    __shared__ float Vs[64 * 68];  // natural V tile [k][d]
    int mb = blockIdx.x * 64;
    int bh = blockIdx.y;
    int tid = threadIdx.x;
    int lrow = tid >> 2;
    int lc0 = (tid & 3) << 4;
    int ty = tid >> 4, tx = tid & 15;

    float acc[4][4];
#pragma unroll
    for (int i = 0; i < 4; i++)
#pragma unroll
        for (int j = 0; j < 4; j++) acc[i][j] = 0.f;

    for (int k0 = 0; k0 < 1024; k0 += 64) {
        const float* ap = attn + (size_t)(bh * 1024 + mb + lrow) * 1024 + k0 + lc0;
#pragma unroll
        for (int i = 0; i < 16; i += 4) {
            float4 av = *(const float4*)(ap + i);
            At[(lc0 + i + 0) * 68 + lrow] = av.x;
            At[(lc0 + i + 1) * 68 + lrow] = av.y;
            At[(lc0 + i + 2) * 68 + lrow] = av.z;
            At[(lc0 + i + 3) * 68 + lrow] = av.w;
        }
        const float* vp = g_v + (size_t)(bh * 1024 + k0 + lrow) * 64 + lc0;
#pragma unroll
        for (int i = 0; i < 16; i += 4) {
            *(float4*)(Vs + lrow * 68 + lc0 + i) = *(const float4*)(vp + i);
        }
        __syncthreads();
#pragma unroll
        for (int kk = 0; kk < 64; kk++) {
            float4 a = *(const float4*)(At + kk * 68 + ty * 4);
            float4 b = *(const float4*)(Vs + kk * 68 + tx * 4);
            float av4[4] = {a.x, a.y, a.z, a.w};
            float bv4[4] = {b.x, b.y, b.z, b.w};
#pragma unroll
            for (int i = 0; i < 4; i++)
#pragma unroll
                for (int j = 0; j < 4; j++) acc[i][j] = fmaf(av4[i], bv4[j], acc[i][j]);
        }
        __syncthreads();
    }

    int b = bh >> 3, h = bh & 7;
#pragma unroll
    for (int i = 0; i < 4; i++) {
        int n = mb + ty * 4 + i;
        float4 o = {acc[i][0], acc[i][1], acc[i][2], acc[i][3]};
        *(float4*)(g_ao + (size_t)(b * 1024 + n) * 512 + h * 64 + tx * 4) = o;
    }
}

// ---------------------------------------------------------------------------
// Kernel 5: proj GEMM + bias + residual.  g_ao[4096,512] @ Wproj[512,512]
// ---------------------------------------------------------------------------
__global__ __launch_bounds__(256) void k_proj(const float* __restrict__ x,
                                              const float* __restrict__ Bm,
                                              const float* __restrict__ bias) {
    const int K = 512, Nn = 512;
    __shared__ float As[8][128];
    __shared__ float Bs[8][128];
    int tid = threadIdx.x;
    int bx = blockIdx.x, by = blockIdx.y;
    int aRow = tid >> 1, aCol = (tid & 1) << 2;
    int bRow = tid >> 5, bCol = (tid & 31) << 2;
    int ty = tid >> 4, tx = tid & 15;

    float acc[8][8];
#pragma unroll
    for (int i = 0; i < 8; i++)
#pragma unroll
        for (int j = 0; j < 8; j++) acc[i][j] = 0.f;

    const float* Ap = g_ao + (size_t)(by * 128 + aRow) * K + aCol;
    const float* Bp = Bm + (size_t)bRow * Nn + bx * 128 + bCol;

    for (int k0 = 0; k0 < K; k0 += 8) {
        float4 av = *(const float4*)(Ap + k0);
        As[aCol + 0][aRow] = av.x;
        As[aCol + 1][aRow] = av.y;
        As[aCol + 2][aRow] = av.z;
        As[aCol + 3][aRow] = av.w;
        *(float4*)&Bs[bRow][bCol] = *(const float4*)(Bp + (size_t)k0 * Nn);
        __syncthreads();
#pragma unroll
        for (int k = 0; k < 8; k++) {
            float a[8], b[8];
            *(float4*)&a[0] = *(const float4*)&As[k][ty * 8];
            *(float4*)&a[4] = *(const float4*)&As[k][ty * 8 + 4];
            *(float4*)&b[0] = *(const float4*)&Bs[k][tx * 8];
            *(float4*)&b[4] = *(const float4*)&Bs[k][tx * 8 + 4];
#pragma unroll
            for (int i = 0; i < 8; i++)
#pragma unroll
                for (int j = 0; j < 8; j++) acc[i][j] = fmaf(a[i], b[j], acc[i][j]);
        }
        __syncthreads();
    }

#pragma unroll
    for (int i = 0; i < 8; i++) {
        int r = by * 128 + ty * 8 + i;
#pragma unroll
        for (int j = 0; j < 8; j++) {
            int c = bx * 128 + tx * 8 + j;
            g_yp[(size_t)r * 512 + c] = acc[i][j] + bias[c] + x[(size_t)r * 512 + c];
        }
    }
}

// ---------------------------------------------------------------------------
// Kernel 6: LayerNorm over last dim (512), write y to d_out.
// ---------------------------------------------------------------------------
__global__ __launch_bounds__(128) void k_ln(const float* __restrict__ gamma,
                                            const float* __restrict__ beta,
                                            float* __restrict__ y) {
    __shared__ float s1[4], s2[4];
    int row = blockIdx.x;
    int tid = threadIdx.x;
    const float* p = g_yp + (size_t)row * 512;
    float4 v = *(const float4*)(p + tid * 4);

    float s = v.x + v.y + v.z + v.w;
    float ss = v.x * v.x + v.y * v.y + v.z * v.z + v.w * v.w;
#pragma unroll
    for (int o = 16; o; o >>= 1) {
        s += __shfl_xor_sync(0xffffffffu, s, o);
        ss += __shfl_xor_sync(0xffffffffu, ss, o);
    }
    int wid = tid >> 5, lane = tid & 31;
    if (lane == 0) { s1[wid] = s; s2[wid] = ss; }
    __syncthreads();
    if (tid == 0) {
        s1[0] = s1[0] + s1[1] + s1[2] + s1[3];
        s2[0] = s2[0] + s2[1] + s2[2] + s2[3];
    }
    __syncthreads();
    float mu = s1[0] * (1.f / 512.f);
    float var = s2[0] * (1.f / 512.f) - mu * mu;
    float rstd = rsqrtf(var + LN_EPSq);

    int c = tid * 4;
    float4 g = *(const float4*)(gamma + c);
    float4 be = *(const float4*)(beta + c);
    float4 o;
    o.x = (v.x - mu) * rstd * g.x + be.x;
    o.y = (v.y - mu) * rstd * g.y + be.y;
    o.z = (v.z - mu) * rstd * g.z + be.z;
    o.w = (v.w - mu) * rstd * g.w + be.w;
    *(float4*)(y + (size_t)row * 512 + c) = o;
}

// ---------------------------------------------------------------------------
extern "C" void kernel_launch(void* const* d_in, const int* in_sizes, int n_in,
                              void* d_out, int out_size) {
    (void)in_sizes; (void)n_in; (void)out_size;
    const float* x     = (const float*)d_in[0];
    const float* Wqkv  = (const float*)d_in[1];
    const float* bqkv  = (const float*)d_in[2];
    const float* ow    = (const float*)d_in[3];
    const float* Wproj = (const float*)d_in[4];
    const float* bproj = (const float*)d_in[5];
    const float* gamma = (const float*)d_in[6];
    const float* beta  = (const float*)d_in[7];

    float* out      = (float*)d_out;
    float* y_out    = out;                       // [4,1024,512]
    float* attn_out = out + (size_t)Bq * Nq * Cq; // [4,8,1024,1024]

    k_qkv    <<<dim3(12, 32), 256>>>(x, Wqkv, bqkv);
    k_scores <<<dim3(16, 16, 32), 256>>>(ow, attn_out);
    k_softmax<<<32768, 256>>>(attn_out);
    k_av     <<<dim3(16, 32), 256>>>(attn_out);
    k_proj   <<<dim3(4, 32), 256>>>(x, Wproj, bproj);
    k_ln     <<<4096, 128>>>(gamma, beta, y_out);
}